// round 8
// baseline (speedup 1.0000x reference)
#include <cuda_runtime.h>
#include <cuda_pipeline.h>

// Problem dims
#define DM     1792           // D_MODEL
#define BBDIM  256            // BB
#define I_DIM  2048           // inner dim I
#define G_DIM  8192           // 4*I

// Streaming config
#define CHUNK   256                   // floats of K per pipeline stage
#define STAGES  4                     // smem ring depth
#define NROWS   8                     // rows processed per block
#define STAGE_F (NROWS * CHUNK)       // floats per stage (2048 = 8KB)

// Scratch state (allocation-free rule: __device__ globals)
__device__ float g_z[6 * G_DIM];      // gate preactivations (Wih part + both biases)
__device__ float g_h[2][I_DIM];       // ping-pong hidden state
__device__ float g_c[2][I_DIM];       // ping-pong cell state

__device__ __forceinline__ float sigmoidf_(float x) {
    return 1.0f / (1.0f + expf(-x));
}

__device__ __forceinline__ float dot4(float4 a, float4 b) {
    return a.x * b.x + a.y * b.y + a.z * b.z + a.w * b.w;
}

__device__ __forceinline__ void warp_sum2(float& a, float& b) {
#pragma unroll
    for (int o = 16; o > 0; o >>= 1) {
        a += __shfl_xor_sync(0xffffffffu, a, o);
        b += __shfl_xor_sync(0xffffffffu, b, o);
    }
}

// ---------------------------------------------------------------------------
// Core: stream 8 rows x (NCHUNK*256) floats through a 4-stage cp.async smem
// ring. Staging lives in SMEM (not RF) -> ~3 stages x 8KB in flight per block
// continuously. Each thread owns 4 fixed 16B units per stage:
//   unit u = tid + i*128  ->  local row u>>6, float4 offset u&63.
// p0..p3 are this thread's 4 gmem srcs at chunk 0 (local rows lr, lr+2, lr+4,
// lr+6 with lr = tid>>6). Warp w reduces local rows 2w and 2w+1 into accA/accB.
// ---------------------------------------------------------------------------
template <int NCHUNK>
__device__ __forceinline__ void stream8(
    const float* p0, const float* p1, const float* p2, const float* p3,
    float* __restrict__ stage, const float* __restrict__ vsm,
    int tid, int w, int lane, float& accA, float& accB)
{
    const int u0 = tid, u1 = tid + 128, u2 = tid + 256, u3 = tid + 384;
    accA = 0.f; accB = 0.f;

    // prologue: stages 0..2
#pragma unroll
    for (int p = 0; p < 3; ++p) {
        if (p < NCHUNK) {
            float* d = stage + p * STAGE_F;
            __pipeline_memcpy_async(d + u0 * 4, p0 + p * CHUNK, 16);
            __pipeline_memcpy_async(d + u1 * 4, p1 + p * CHUNK, 16);
            __pipeline_memcpy_async(d + u2 * 4, p2 + p * CHUNK, 16);
            __pipeline_memcpy_async(d + u3 * 4, p3 + p * CHUNK, 16);
        }
        __pipeline_commit();
    }

#pragma unroll
    for (int s = 0; s < NCHUNK; ++s) {
        __pipeline_wait_prior(2);      // stage s arrived (own copies)
        __syncthreads();               // visibility + slot (s-1)%4 free
        if (s + 3 < NCHUNK) {          // refill slot (s+3)%4
            float* d = stage + ((s + 3) % STAGES) * STAGE_F;
            __pipeline_memcpy_async(d + u0 * 4, p0 + (s + 3) * CHUNK, 16);
            __pipeline_memcpy_async(d + u1 * 4, p1 + (s + 3) * CHUNK, 16);
            __pipeline_memcpy_async(d + u2 * 4, p2 + (s + 3) * CHUNK, 16);
            __pipeline_memcpy_async(d + u3 * 4, p3 + (s + 3) * CHUNK, 16);
        }
        __pipeline_commit();           // uniform group count (may be empty)

        const float4* st4 = (const float4*)(stage + (s % STAGES) * STAGE_F);
        const float4* v4  = (const float4*)vsm + s * 64;
        float4 va = v4[lane];
        float4 vb = v4[lane + 32];
        const float4* ra = st4 + (2 * w) * 64;
        const float4* rb = ra + 64;
        accA += dot4(ra[lane], va) + dot4(ra[lane + 32], vb);
        accB += dot4(rb[lane], va) + dot4(rb[lane + 32], vb);
    }
}

// ---------------------------------------------------------------------------
// K0: z for cells 0 and 1. 2048 blocks x 128 thr; block = 8 consecutive rows.
// ---------------------------------------------------------------------------
__global__ void __launch_bounds__(128, 5) k0_kernel(
    const float* __restrict__ x,     // (6, 1792)
    const float* __restrict__ y,     // (5, 256)
    const float* __restrict__ Wih5,  // (5, 8192, 2048)
    const float* __restrict__ bih5,  // (5, 8192)
    const float* __restrict__ bhh5)  // (5, 8192)
{
    __shared__ float vsm[I_DIM];
    __shared__ float stage[STAGES * STAGE_F];

    const int tid = threadIdx.x, w = tid >> 5, lane = tid & 31;
    const int t    = blockIdx.x >> 10;             // cell 0 or 1
    const int r0   = (blockIdx.x & 1023) * NROWS;  // first of 8 rows
    const int lr   = tid >> 6;
    const int off  = (tid & 63) * 4;

    for (int k = tid; k < DM; k += 128)    vsm[k]      = x[t * DM + k];
    for (int k = tid; k < BBDIM; k += 128) vsm[DM + k] = y[t * BBDIM + k];

    const float* Wb = Wih5 + (size_t)t * G_DIM * I_DIM;
    const float* p0 = Wb + (size_t)(r0 + lr)     * I_DIM + off;
    const float* p1 = Wb + (size_t)(r0 + lr + 2) * I_DIM + off;
    const float* p2 = Wb + (size_t)(r0 + lr + 4) * I_DIM + off;
    const float* p3 = Wb + (size_t)(r0 + lr + 6) * I_DIM + off;

    float aA, aB;
    stream8<8>(p0, p1, p2, p3, stage, vsm, tid, w, lane, aA, aB);
    warp_sum2(aA, aB);

    if (lane == 0) {
        const size_t zb = (size_t)t * G_DIM + r0;
        const int rA = 2 * w, rB = 2 * w + 1;
        g_z[zb + rA] = aA + bih5[zb + rA] + bhh5[zb + rA];
        g_z[zb + rB] = aB + bih5[zb + rB] + bhh5[zb + rB];
    }
}

// ---------------------------------------------------------------------------
// step 0: h0 = c0 = 0 -> Whh contributes nothing, f*c0 = 0. (skips Whh5[0])
// ---------------------------------------------------------------------------
__global__ void step0_kernel() {
    int j = blockIdx.x * blockDim.x + threadIdx.x;
    if (j >= I_DIM) return;
    float zi = g_z[j];
    float zg = g_z[2 * I_DIM + j];
    float zo = g_z[3 * I_DIM + j];
    float c  = sigmoidf_(zi) * tanhf(zg);
    float h  = sigmoidf_(zo) * tanhf(c);
    g_c[0][j] = c;
    g_h[0][j] = h;
}

// ---------------------------------------------------------------------------
// Fused step. Blocks [0,1024): recurrent — block = 2 j's x 4 gates (8 rows),
// warp w = gate w for both j's; gate math by threads 0,1 after a smem gather.
// Blocks >= 1024: z-precompute for the next cell (8 consecutive rows).
// mode 0: z = full cell t+1 (8192 rows -> 1024 z-blocks, K=2048)
// mode 1: z = final-cell slice (1024 rows of WihF -> 128 z-blocks, K=1792)
// ---------------------------------------------------------------------------
__global__ void __launch_bounds__(128, 5) fused_step(
    const float* __restrict__ whh,   // (8192, 2048) Whh for step t
    int zoff, int pin, int pout,
    const float* __restrict__ wz,    // Wih for next cell
    const float* __restrict__ xvec,  // x row for next cell
    const float* __restrict__ yvec,  // y row for next cell (null in mode 1)
    const float* __restrict__ bih,   // bih for next cell
    const float* __restrict__ bhh,   // bhh for next cell
    int zout, int mode)
{
    __shared__ float vsm[I_DIM];
    __shared__ float stage[STAGES * STAGE_F];
    __shared__ float dots[8];

    const int tid = threadIdx.x, w = tid >> 5, lane = tid & 31;
    const int lr  = tid >> 6;
    const int off = (tid & 63) * 4;

    if (blockIdx.x < 1024) {
        // ---------------- recurrent role: 2 j's, 4 gates ------------------
        const int j0 = blockIdx.x * 2;
        {
            const float4* gh4 = (const float4*)g_h[pin];
            float4* s4 = (float4*)vsm;
#pragma unroll
            for (int k = 0; k < 4; ++k) s4[tid + k * 128] = gh4[tid + k * 128];
        }
        // local row lrI = gate*2 + jj  ->  gmem row gate*2048 + j0 + jj
        const float* p0 = whh + (size_t)(((lr    ) >> 1) * I_DIM + j0 + ((lr    ) & 1)) * I_DIM + off;
        const float* p1 = whh + (size_t)(((lr + 2) >> 1) * I_DIM + j0 + ((lr + 2) & 1)) * I_DIM + off;
        const float* p2 = whh + (size_t)(((lr + 4) >> 1) * I_DIM + j0 + ((lr + 4) & 1)) * I_DIM + off;
        const float* p3 = whh + (size_t)(((lr + 6) >> 1) * I_DIM + j0 + ((lr + 6) & 1)) * I_DIM + off;

        float aA, aB;
        stream8<8>(p0, p1, p2, p3, stage, vsm, tid, w, lane, aA, aB);
        warp_sum2(aA, aB);
        if (lane == 0) { dots[2 * w] = aA; dots[2 * w + 1] = aB; }  // [gate*2+jj]
        __syncthreads();

        if (tid < 2) {
            const int j = j0 + tid;
            const float* z = g_z + zoff;
            float gi = z[j]             + dots[0 + tid];
            float gf = z[I_DIM + j]     + dots[2 + tid];
            float gg = z[2 * I_DIM + j] + dots[4 + tid];
            float go = z[3 * I_DIM + j] + dots[6 + tid];
            float c  = sigmoidf_(gf) * g_c[pin][j] + sigmoidf_(gi) * tanhf(gg);
            float h  = sigmoidf_(go) * tanhf(c);
            g_c[pout][j] = c;
            g_h[pout][j] = h;
        }
    } else {
        // ---------------- z-precompute role ------------------------------
        const int q = blockIdx.x - 1024;

        if (mode == 0) {
            for (int k = tid; k < DM; k += 128)    vsm[k]      = xvec[k];
            for (int k = tid; k < BBDIM; k += 128) vsm[DM + k] = yvec[k];

            const int r0 = q * NROWS;
            const float* p0 = wz + (size_t)(r0 + lr)     * I_DIM + off;
            const float* p1 = wz + (size_t)(r0 + lr + 2) * I_DIM + off;
            const float* p2 = wz + (size_t)(r0 + lr + 4) * I_DIM + off;
            const float* p3 = wz + (size_t)(r0 + lr + 6) * I_DIM + off;

            float aA, aB;
            stream8<8>(p0, p1, p2, p3, stage, vsm, tid, w, lane, aA, aB);
            warp_sum2(aA, aB);
            if (lane == 0) {
                const int rA = r0 + 2 * w, rB = rA + 1;
                g_z[zout + rA] = aA + bih[rA] + bhh[rA];
                g_z[zout + rB] = aB + bih[rB] + bhh[rB];
            }
        } else {
            for (int k = tid; k < DM; k += 128) vsm[k] = xvec[k];

            const int rl0 = q * NROWS;                 // 0..1016
            const int g   = rl0 >> 8;
            const int jj0 = rl0 & 255;
            const int r0  = g * I_DIM + DM + jj0;      // 8 consecutive rows
            const float* p0 = wz + (size_t)(r0 + lr)     * DM + off;
            const float* p1 = wz + (size_t)(r0 + lr + 2) * DM + off;
            const float* p2 = wz + (size_t)(r0 + lr + 4) * DM + off;
            const float* p3 = wz + (size_t)(r0 + lr + 6) * DM + off;

            float aA, aB;
            stream8<7>(p0, p1, p2, p3, stage, vsm, tid, w, lane, aA, aB);
            warp_sum2(aA, aB);
            if (lane == 0) {
                const int rA = r0 + 2 * w, rB = rA + 1;
                g_z[zout + rA] = aA + bih[rA] + bhh[rA];
                g_z[zout + rB] = aB + bih[rB] + bhh[rB];
            }
        }
    }
}

// ---------------------------------------------------------------------------
// Final step: only j in [1792, 2048). 128 blocks; block = 2 j's x 4 gates of
// WhhF, same layout as rec role. Writes d_out directly.
// ---------------------------------------------------------------------------
__global__ void __launch_bounds__(128, 5) final_step(
    const float* __restrict__ whhF,  // (8192, 2048)
    int pin,
    float* __restrict__ out)
{
    __shared__ float vsm[I_DIM];
    __shared__ float stage[STAGES * STAGE_F];
    __shared__ float dots[8];

    const int tid = threadIdx.x, w = tid >> 5, lane = tid & 31;
    const int lr  = tid >> 6;
    const int off = (tid & 63) * 4;

    {
        const float4* gh4 = (const float4*)g_h[pin];
        float4* s4 = (float4*)vsm;
#pragma unroll
        for (int k = 0; k < 4; ++k) s4[tid + k * 128] = gh4[tid + k * 128];
    }

    const int j0 = DM + blockIdx.x * 2;            // 1792 .. 2046
    const float* p0 = whhF + (size_t)(((lr    ) >> 1) * I_DIM + j0 + ((lr    ) & 1)) * I_DIM + off;
    const float* p1 = whhF + (size_t)(((lr + 2) >> 1) * I_DIM + j0 + ((lr + 2) & 1)) * I_DIM + off;
    const float* p2 = whhF + (size_t)(((lr + 4) >> 1) * I_DIM + j0 + ((lr + 4) & 1)) * I_DIM + off;
    const float* p3 = whhF + (size_t)(((lr + 6) >> 1) * I_DIM + j0 + ((lr + 6) & 1)) * I_DIM + off;

    float aA, aB;
    stream8<8>(p0, p1, p2, p3, stage, vsm, tid, w, lane, aA, aB);
    warp_sum2(aA, aB);
    if (lane == 0) { dots[2 * w] = aA; dots[2 * w + 1] = aB; }
    __syncthreads();

    if (tid < 2) {
        const int j = j0 + tid;
        const float* z = g_z + 5 * G_DIM;
        float gi = z[j]             + dots[0 + tid];
        float gf = z[I_DIM + j]     + dots[2 + tid];
        float gg = z[2 * I_DIM + j] + dots[4 + tid];
        float go = z[3 * I_DIM + j] + dots[6 + tid];
        float c  = sigmoidf_(gf) * g_c[pin][j] + sigmoidf_(gi) * tanhf(gg);
        float h  = sigmoidf_(go) * tanhf(c);
        out[j - DM] = h;
    }
}

// ---------------------------------------------------------------------------
extern "C" void kernel_launch(void* const* d_in, const int* in_sizes, int n_in,
                              void* d_out, int out_size)
{
    const float* x    = (const float*)d_in[0];
    const float* y    = (const float*)d_in[1];
    const float* Wih5 = (const float*)d_in[2];
    const float* Whh5 = (const float*)d_in[3];
    const float* bih5 = (const float*)d_in[4];
    const float* bhh5 = (const float*)d_in[5];
    const float* WihF = (const float*)d_in[6];
    const float* WhhF = (const float*)d_in[7];
    const float* bihF = (const float*)d_in[8];
    const float* bhhF = (const float*)d_in[9];
    float* out = (float*)d_out;

    (void)in_sizes; (void)n_in; (void)out_size;

    const size_t WSTEP = (size_t)G_DIM * I_DIM;    // elems per (8192,2048) matrix

    // K0: z[0] and z[1] (134 MB, fully parallel)
    k0_kernel<<<2048, 128>>>(x, y, Wih5, bih5, bhh5);

    // step 0 (h0=c0=0: no Whh read)
    step0_kernel<<<(I_DIM + 255) / 256, 256>>>();

    // S1..S3: step t fused with z-precompute for cell t+1 (134 MB each)
    int pin = 0;
    for (int t = 1; t <= 3; ++t) {
        fused_step<<<1024 + 1024, 128>>>(
            Whh5 + (size_t)t * WSTEP, t * G_DIM, pin, 1 - pin,
            Wih5 + (size_t)(t + 1) * WSTEP,
            x + (t + 1) * DM, y + (t + 1) * BBDIM,
            bih5 + (size_t)(t + 1) * G_DIM, bhh5 + (size_t)(t + 1) * G_DIM,
            (t + 1) * G_DIM, /*mode=*/0);
        pin = 1 - pin;
    }

    // S4: step 4 fused with the FINAL-cell z slice (67 + 7.3 MB)
    fused_step<<<1024 + 128, 128>>>(
        Whh5 + (size_t)4 * WSTEP, 4 * G_DIM, pin, 1 - pin,
        WihF, x + 5 * DM, nullptr,
        bihF, bhhF, 5 * G_DIM, /*mode=*/1);
    pin = 1 - pin;

    // S5: final step, sliced to the 256 needed outputs (8.4 MB)
    final_step<<<128, 128>>>(WhhF, pin, out);
}

// round 9
// speedup vs baseline: 1.1590x; 1.1590x over previous
#include <cuda_runtime.h>

// Problem dims
#define DM     1792           // D_MODEL
#define BBDIM  256            // BB
#define I_DIM  2048           // inner dim I
#define G_DIM  8192           // 4*I
#define NBLK   1024           // persistent grid (one wave: <= 148*7)

#define GS4 ((size_t)I_DIM * I_DIM / 4)   // gate stride in float4

// Scratch state (allocation-free rule: __device__ globals)
__device__ float g_z[6 * G_DIM];      // gate preactivations (Wih part + biases)
__device__ float g_h[2][I_DIM];       // ping-pong hidden state
__device__ unsigned g_bar_count;      // grid barrier arrivals (self-resetting)
__device__ unsigned g_bar_epoch;      // grid barrier epoch (monotonic)

__device__ __forceinline__ float sigmoidf_(float x) {
    return 1.0f / (1.0f + expf(-x));
}
__device__ __forceinline__ float dot4(float4 a, float4 b) {
    return a.x * b.x + a.y * b.y + a.z * b.z + a.w * b.w;
}

// ---------------------------------------------------------------------------
// Epoch-based software grid barrier. Safe: grid is exactly one resident wave.
// Replay-deterministic: count self-resets to 0; epoch grows monotonically and
// each block reads its base epoch at kernel entry (stable until 1st barrier).
// ---------------------------------------------------------------------------
__device__ __forceinline__ void grid_barrier(unsigned target) {
    __syncthreads();
    if (threadIdx.x == 0) {
        __threadfence();                       // release my phase's writes
        unsigned prev = atomicAdd(&g_bar_count, 1u);
        if (prev == NBLK - 1) {
            g_bar_count = 0;
            __threadfence();
            atomicAdd(&g_bar_epoch, 1u);
        } else {
            while (*(volatile unsigned*)&g_bar_epoch < target) __nanosleep(64);
        }
        __threadfence();                       // acquire others' writes
    }
    __syncthreads();
}

// ---------------------------------------------------------------------------
// Quad-row warp dot (register double-buffer, distance-2 prefetch): one warp
// streams 4 weight rows vs one smem vector; 8-12 LDG.128 in flight.
// ---------------------------------------------------------------------------
template <int NITER>
__device__ __forceinline__ void quad_dot(const float4* __restrict__ r0,
                                         const float4* __restrict__ r1,
                                         const float4* __restrict__ r2,
                                         const float4* __restrict__ r3,
                                         const float4* __restrict__ v4,
                                         int lane, float acc[4])
{
    float4 a0 = __ldcs(r0 + lane),      a1 = __ldcs(r1 + lane),
           a2 = __ldcs(r2 + lane),      a3 = __ldcs(r3 + lane);
    float4 b0 = __ldcs(r0 + lane + 32), b1 = __ldcs(r1 + lane + 32),
           b2 = __ldcs(r2 + lane + 32), b3 = __ldcs(r3 + lane + 32);

    acc[0] = acc[1] = acc[2] = acc[3] = 0.f;

#pragma unroll
    for (int k = 0; k < NITER; ++k) {
        float4 n0, n1, n2, n3;
        if (k + 2 < NITER) {
            n0 = __ldcs(r0 + lane + (k + 2) * 32);
            n1 = __ldcs(r1 + lane + (k + 2) * 32);
            n2 = __ldcs(r2 + lane + (k + 2) * 32);
            n3 = __ldcs(r3 + lane + (k + 2) * 32);
        }
        float4 h = v4[lane + k * 32];
        acc[0] += dot4(a0, h);
        acc[1] += dot4(a1, h);
        acc[2] += dot4(a2, h);
        acc[3] += dot4(a3, h);
        if (k + 1 < NITER) { a0 = b0; a1 = b1; a2 = b2; a3 = b3; }
        if (k + 2 < NITER) { b0 = n0; b1 = n1; b2 = n2; b3 = n3; }
    }
}

__device__ __forceinline__ void warp_sum4(float acc[4]) {
#pragma unroll
    for (int o = 16; o > 0; o >>= 1) {
        acc[0] += __shfl_xor_sync(0xffffffffu, acc[0], o);
        acc[1] += __shfl_xor_sync(0xffffffffu, acc[1], o);
        acc[2] += __shfl_xor_sync(0xffffffffu, acc[2], o);
        acc[3] += __shfl_xor_sync(0xffffffffu, acc[3], o);
    }
}

// ---------------------------------------------------------------------------
// z-role: 4 consecutive rows of a (G_DIM x 2048) Wih vs vsm (x||y staged).
// ---------------------------------------------------------------------------
__device__ __forceinline__ void zrole_full(const float* __restrict__ Wb,
                                           const float* __restrict__ xv,
                                           const float* __restrict__ yv,
                                           const float* __restrict__ bih,
                                           const float* __restrict__ bhh,
                                           int zout, int lb, float* vsm,
                                           int tid, int w, int lane)
{
    for (int k = tid; k < DM; k += 128)    vsm[k]      = xv[k];
    for (int k = tid; k < BBDIM; k += 128) vsm[DM + k] = yv[k];
    __syncthreads();

    const int r = ((lb << 2) + w) << 2;
    const float4* r0 = (const float4*)(Wb + (size_t)r * I_DIM);
    float acc[4];
    quad_dot<16>(r0, r0 + 512, r0 + 1024, r0 + 1536, (const float4*)vsm, lane, acc);
    warp_sum4(acc);
    if (lane == 0) {
#pragma unroll
        for (int u = 0; u < 4; ++u)
            g_z[zout + r + u] = acc[u] + bih[r + u] + bhh[r + u];
    }
}

// ---------------------------------------------------------------------------
// Persistent kernel: all 6 LSTM cells in one launch.
// bid<512: rec lane for j = bid*4+w (cell state carried in register cj).
// bid>=512: z-precompute lane for the next cell.
// ---------------------------------------------------------------------------
__global__ void __launch_bounds__(128, 7) lstm_all(
    const float* __restrict__ x,     // (6, 1792)
    const float* __restrict__ y,     // (5, 256)
    const float* __restrict__ Wih5,  // (5, 8192, 2048)
    const float* __restrict__ Whh5,  // (5, 8192, 2048)
    const float* __restrict__ bih5,  // (5, 8192)
    const float* __restrict__ bhh5,  // (5, 8192)
    const float* __restrict__ WihF,  // (8192, 1792)
    const float* __restrict__ WhhF,  // (8192, 2048)
    const float* __restrict__ bihF,  // (8192)
    const float* __restrict__ bhhF,  // (8192)
    float* __restrict__ out)         // (256)
{
    __shared__ float vsm[I_DIM];

    const int tid  = threadIdx.x;
    const int w    = tid >> 5;
    const int lane = tid & 31;
    const int bid  = blockIdx.x;
    const size_t WSTEP = (size_t)G_DIM * I_DIM;

    const unsigned e0 = *(volatile unsigned*)&g_bar_epoch;  // stable at entry

    // ==================== Phase A: z0 + z1 (all blocks) ====================
    {
        const int t  = bid >> 9;                 // cell 0 or 1
        const int lb = bid & 511;
        zrole_full(Wih5 + (size_t)t * WSTEP, x + t * DM, y + t * BBDIM,
                   bih5 + (size_t)t * G_DIM, bhh5 + (size_t)t * G_DIM,
                   t * G_DIM, lb, vsm, tid, w, lane);
    }
    grid_barrier(e0 + 1);

    float cj = 0.f;                              // register cell state (j = bid*4+w)
    const int j = (bid << 2) + w;                // rec j for bid<512

    // ==================== Phase B: rec1 (+ h0 inline) | z2 =================
    if (bid < 512) {
        // h0 = sig(zo0)*tanh(sig(zi0)*tanh(zg0)) computed elementwise (L2-hot)
        for (int k = tid; k < I_DIM; k += 128) {
            float zi = __ldcg(g_z + k);
            float zg = __ldcg(g_z + 2 * I_DIM + k);
            float zo = __ldcg(g_z + 3 * I_DIM + k);
            float c0 = sigmoidf_(zi) * tanhf(zg);
            vsm[k] = sigmoidf_(zo) * tanhf(c0);
        }
        __syncthreads();

        // init my cj = c0[j]
        {
            float zi = __ldcg(g_z + j);
            float zg = __ldcg(g_z + 2 * I_DIM + j);
            cj = sigmoidf_(zi) * tanhf(zg);
        }

        const float4* r0 = (const float4*)(Whh5 + 1 * WSTEP + (size_t)j * I_DIM);
        float acc[4];
        quad_dot<16>(r0, r0 + GS4, r0 + 2 * GS4, r0 + 3 * GS4,
                     (const float4*)vsm, lane, acc);
        warp_sum4(acc);

        const float* z = g_z + 1 * G_DIM;
        float gi = __ldcg(z + j)             + acc[0];
        float gf = __ldcg(z + I_DIM + j)     + acc[1];
        float gg = __ldcg(z + 2 * I_DIM + j) + acc[2];
        float go = __ldcg(z + 3 * I_DIM + j) + acc[3];
        cj = sigmoidf_(gf) * cj + sigmoidf_(gi) * tanhf(gg);
        if (lane == 0) g_h[1][j] = sigmoidf_(go) * tanhf(cj);
    } else {
        zrole_full(Wih5 + 2 * WSTEP, x + 2 * DM, y + 2 * BBDIM,
                   bih5 + 2 * G_DIM, bhh5 + 2 * G_DIM,
                   2 * G_DIM, bid - 512, vsm, tid, w, lane);
    }
    grid_barrier(e0 + 2);

    // ==================== Phases C, D, E: rec t | z(t+1) ===================
#pragma unroll
    for (int t = 2; t <= 4; ++t) {
        const int bufin  = (t - 1) & 1;          // h(t-1) buffer
        const int bufout = t & 1 ? 1 : 0;        // t=2->0, t=3->1, t=4->0
        if (bid < 512) {
            const float4* gh4 = (const float4*)g_h[bufin];
            float4* s4 = (float4*)vsm;
#pragma unroll
            for (int k2 = 0; k2 < 4; ++k2)
                s4[tid + k2 * 128] = __ldcg(gh4 + tid + k2 * 128);
            __syncthreads();

            const float4* r0 = (const float4*)(Whh5 + (size_t)t * WSTEP + (size_t)j * I_DIM);
            float acc[4];
            quad_dot<16>(r0, r0 + GS4, r0 + 2 * GS4, r0 + 3 * GS4,
                         (const float4*)vsm, lane, acc);
            warp_sum4(acc);

            const float* z = g_z + (size_t)t * G_DIM;
            float gi = __ldcg(z + j)             + acc[0];
            float gf = __ldcg(z + I_DIM + j)     + acc[1];
            float gg = __ldcg(z + 2 * I_DIM + j) + acc[2];
            float go = __ldcg(z + 3 * I_DIM + j) + acc[3];
            cj = sigmoidf_(gf) * cj + sigmoidf_(gi) * tanhf(gg);
            if (lane == 0) g_h[bufout][j] = sigmoidf_(go) * tanhf(cj);
        } else if (t < 4) {
            // z for cell t+1 (full)
            zrole_full(Wih5 + (size_t)(t + 1) * WSTEP, x + (t + 1) * DM,
                       y + (t + 1) * BBDIM,
                       bih5 + (size_t)(t + 1) * G_DIM, bhh5 + (size_t)(t + 1) * G_DIM,
                       (t + 1) * G_DIM, bid - 512, vsm, tid, w, lane);
        } else if (bid < 576) {
            // zF slice: rows gate*2048 + [1792,2048) of WihF, K=1792
            for (int k = tid; k < DM; k += 128) vsm[k] = x[5 * DM + k];
            __syncthreads();

            const int lb = bid - 512;                // 0..63
            const int rl = ((lb << 2) + w) << 2;     // 0..1020
            const int g  = rl >> 8;
            const int jj = rl & 255;
            const int r  = g * I_DIM + DM + jj;      // 4 consecutive rows
            const float4* r0 = (const float4*)(WihF + (size_t)r * DM);
            float acc[4];
            quad_dot<14>(r0, r0 + 448, r0 + 896, r0 + 1344,
                         (const float4*)vsm, lane, acc);
            warp_sum4(acc);
            if (lane == 0) {
#pragma unroll
                for (int u = 0; u < 4; ++u)
                    g_z[5 * G_DIM + r + u] = acc[u] + bihF[r + u] + bhhF[r + u];
            }
        }
        grid_barrier(e0 + t + 1);
    }

    // ==================== Phase F: final cell, j in [1792,2048) ============
    // Blocks 448..511 already hold c4 for exactly these j's in registers.
    if (bid >= 448 && bid < 512) {
        const float4* gh4 = (const float4*)g_h[0];   // h4
        float4* s4 = (float4*)vsm;
#pragma unroll
        for (int k2 = 0; k2 < 4; ++k2)
            s4[tid + k2 * 128] = __ldcg(gh4 + tid + k2 * 128);
        __syncthreads();

        const float4* r0 = (const float4*)(WhhF + (size_t)j * I_DIM);
        float acc[4];
        quad_dot<16>(r0, r0 + GS4, r0 + 2 * GS4, r0 + 3 * GS4,
                     (const float4*)vsm, lane, acc);
        warp_sum4(acc);

        const float* z = g_z + 5 * G_DIM;
        float gi = __ldcg(z + j)             + acc[0];
        float gf = __ldcg(z + I_DIM + j)     + acc[1];
        float gg = __ldcg(z + 2 * I_DIM + j) + acc[2];
        float go = __ldcg(z + 3 * I_DIM + j) + acc[3];
        float c  = sigmoidf_(gf) * cj + sigmoidf_(gi) * tanhf(gg);
        float h  = sigmoidf_(go) * tanhf(c);
        if (lane == 0) out[j - DM] = h;
    }
}

// ---------------------------------------------------------------------------
extern "C" void kernel_launch(void* const* d_in, const int* in_sizes, int n_in,
                              void* d_out, int out_size)
{
    const float* x    = (const float*)d_in[0];
    const float* y    = (const float*)d_in[1];
    const float* Wih5 = (const float*)d_in[2];
    const float* Whh5 = (const float*)d_in[3];
    const float* bih5 = (const float*)d_in[4];
    const float* bhh5 = (const float*)d_in[5];
    const float* WihF = (const float*)d_in[6];
    const float* WhhF = (const float*)d_in[7];
    const float* bihF = (const float*)d_in[8];
    const float* bhhF = (const float*)d_in[9];
    float* out = (float*)d_out;

    (void)in_sizes; (void)n_in; (void)out_size;

    lstm_all<<<NBLK, 128>>>(x, y, Wih5, Whh5, bih5, bhh5,
                            WihF, WhhF, bihF, bhhF, out);
}